// round 14
// baseline (speedup 1.0000x reference)
#include <cuda_runtime.h>
#include <cuda_bf16.h>
#include <cstdint>

#define B_   16
#define N_   1024
#define DIN_ 256
#define H_   4
#define F_   64
#define OUT_ 256

// -------- scratch (device globals) --------
__device__ float g_h[B_ * N_ * OUT_];        // h fp32 row-major
__device__ float g_esrc[B_ * H_ * N_];
__device__ float g_edst[B_ * H_ * N_];
// Interleaved B-fragment tiles, f-major: per (b, hd, chunk): gt[f*32 + col],
// col = kt*4+cc (j0 = chunk*128 + kt*16 + 2cc), uint4 =
// {hi(j0,j0+1), hi(j0+8,j0+9), lo(j0,j0+1), lo(j0+8,j0+9)}.
__device__ uint4 g_hTi[B_ * H_ * 8 * 2048];

// bf16 split helpers
__device__ __forceinline__ uint32_t hi_pack(float v0, float v1) {
    uint32_t r;
    asm("prmt.b32 %0, %1, %2, 0x7632;" : "=r"(r)
        : "r"(__float_as_uint(v0)), "r"(__float_as_uint(v1)));
    return r;
}
__device__ __forceinline__ uint32_t lo_pack(float v0, float v1) {
    float l0 = v0 - __uint_as_float(__float_as_uint(v0) & 0xFFFF0000u);
    float l1 = v1 - __uint_as_float(__float_as_uint(v1) & 0xFFFF0000u);
    uint32_t r;
    asm("cvt.rn.bf16x2.f32 %0, %1, %2;" : "=r"(r) : "f"(l1), "f"(l0));
    return r;
}

// warp-level bf16 MMA (HMMA path, sm_80+)
__device__ __forceinline__ void mma16816(float* c, uint32_t a0, uint32_t a1,
                                         uint32_t a2, uint32_t a3,
                                         uint32_t b0, uint32_t b1) {
    asm volatile(
        "mma.sync.aligned.m16n8k16.row.col.f32.bf16.bf16.f32 "
        "{%0,%1,%2,%3}, {%4,%5,%6,%7}, {%8,%9}, {%0,%1,%2,%3};"
        : "+f"(c[0]), "+f"(c[1]), "+f"(c[2]), "+f"(c[3])
        : "r"(a0), "r"(a1), "r"(a2), "r"(a3), "r"(b0), "r"(b1));
}

// ============================================================================
// Kernel 1: h = x @ W via split-bf16 HMMA, double-buffered smem stages.
// CTA = 128 rows x 128 cols (2 heads); grid (128, 2); 8 warps.
// Per kt: LDG(kt+1)->regs, MMA on buf[kt&1], STS->buf[(kt+1)&1], ONE sync.
// Epilogue: h fp32 store + fused e_src/e_dst reductions.
// ============================================================================
__global__ __launch_bounds__(256, 2) void gemm_h_mma_kernel(
    const float* __restrict__ x, const float* __restrict__ W,
    const float* __restrict__ a_src, const float* __restrict__ a_dst)
{
    __shared__ uint32_t sxh[2][128 * 12];
    __shared__ uint32_t sxl[2][128 * 12];
    __shared__ uint4    swt[2][128 * 4];
    __shared__ float    sAs[256];
    __shared__ float    sAd[256];

    const int tid = threadIdx.x;
    const int wid = tid >> 5;
    const int l   = tid & 31;
    const int q   = l >> 2;
    const int c   = l & 3;
    const int R0  = blockIdx.x * 128;
    const int F0  = blockIdx.y * 128;

    sAs[tid] = a_src[tid];
    sAd[tid] = a_dst[tid];

    float acc[16][4];
#pragma unroll
    for (int nt = 0; nt < 16; nt++)
#pragma unroll
        for (int k = 0; k < 4; k++) acc[nt][k] = 0.f;

    const int xr = tid >> 1, xh = tid & 1;
    const int wf = tid >> 1, wh = tid & 1;

    float4 pxa, pxb;
    float  pw[2][4];

    // load kt = 0 into regs
    {
        const float* xp = x + (size_t)(R0 + xr) * DIN_ + xh * 8;
        pxa = *(const float4*)xp;
        pxb = *(const float4*)(xp + 4);
#pragma unroll
        for (int t = 0; t < 2; t++) {
            int cc = wh * 2 + t;
            const float* wp = W + (size_t)(2 * cc) * OUT_ + F0 + wf;
            pw[t][0] = wp[0]; pw[t][1] = wp[OUT_];
            pw[t][2] = wp[8 * OUT_]; pw[t][3] = wp[9 * OUT_];
        }
    }
    // store kt = 0 into buf 0
    {
        *(uint4*)&sxh[0][xr * 12 + xh * 4] =
            make_uint4(hi_pack(pxa.x, pxa.y), hi_pack(pxa.z, pxa.w),
                       hi_pack(pxb.x, pxb.y), hi_pack(pxb.z, pxb.w));
        *(uint4*)&sxl[0][xr * 12 + xh * 4] =
            make_uint4(lo_pack(pxa.x, pxa.y), lo_pack(pxa.z, pxa.w),
                       lo_pack(pxb.x, pxb.y), lo_pack(pxb.z, pxb.w));
#pragma unroll
        for (int t = 0; t < 2; t++) {
            int cc = wh * 2 + t;
            swt[0][wf * 4 + cc] =
                make_uint4(hi_pack(pw[t][0], pw[t][1]), hi_pack(pw[t][2], pw[t][3]),
                           lo_pack(pw[t][0], pw[t][1]), lo_pack(pw[t][2], pw[t][3]));
        }
    }
    __syncthreads();

    for (int kt = 0; kt < 16; kt++) {
        const int cur = kt & 1, nxt = cur ^ 1;
        // prefetch kt+1 (LDG overlaps the mma below)
        if (kt < 15) {
            const float* xp = x + (size_t)(R0 + xr) * DIN_ + (kt + 1) * 16 + xh * 8;
            pxa = *(const float4*)xp;
            pxb = *(const float4*)(xp + 4);
#pragma unroll
            for (int t = 0; t < 2; t++) {
                int cc = wh * 2 + t;
                const float* wp = W + (size_t)((kt + 1) * 16 + 2 * cc) * OUT_ + F0 + wf;
                pw[t][0] = wp[0]; pw[t][1] = wp[OUT_];
                pw[t][2] = wp[8 * OUT_]; pw[t][3] = wp[9 * OUT_];
            }
        }

        const int r0 = wid * 16 + q;
        const uint32_t ah0 = sxh[cur][r0 * 12 + c];
        const uint32_t ah1 = sxh[cur][(r0 + 8) * 12 + c];
        const uint32_t ah2 = sxh[cur][r0 * 12 + c + 4];
        const uint32_t ah3 = sxh[cur][(r0 + 8) * 12 + c + 4];
        const uint32_t al0 = sxl[cur][r0 * 12 + c];
        const uint32_t al1 = sxl[cur][(r0 + 8) * 12 + c];
        const uint32_t al2 = sxl[cur][r0 * 12 + c + 4];
        const uint32_t al3 = sxl[cur][(r0 + 8) * 12 + c + 4];

#pragma unroll
        for (int nt = 0; nt < 16; nt++) {
            uint4 v = swt[cur][(nt * 8 + q) * 4 + c];
            mma16816(acc[nt], ah0, ah1, ah2, ah3, v.x, v.y);
            mma16816(acc[nt], ah0, ah1, ah2, ah3, v.z, v.w);
            mma16816(acc[nt], al0, al1, al2, al3, v.x, v.y);
        }

        // stage kt+1 into the other buffer
        if (kt < 15) {
            *(uint4*)&sxh[nxt][xr * 12 + xh * 4] =
                make_uint4(hi_pack(pxa.x, pxa.y), hi_pack(pxa.z, pxa.w),
                           hi_pack(pxb.x, pxb.y), hi_pack(pxb.z, pxb.w));
            *(uint4*)&sxl[nxt][xr * 12 + xh * 4] =
                make_uint4(lo_pack(pxa.x, pxa.y), lo_pack(pxa.z, pxa.w),
                           lo_pack(pxb.x, pxb.y), lo_pack(pxb.z, pxb.w));
#pragma unroll
            for (int t = 0; t < 2; t++) {
                int cc = wh * 2 + t;
                swt[nxt][wf * 4 + cc] =
                    make_uint4(hi_pack(pw[t][0], pw[t][1]), hi_pack(pw[t][2], pw[t][3]),
                               lo_pack(pw[t][0], pw[t][1]), lo_pack(pw[t][2], pw[t][3]));
            }
            __syncthreads();
        }
    }

    // ---- epilogue: store h fp32 + e_src/e_dst reductions ----
    const int gr0 = R0 + wid * 16 + q;
#pragma unroll
    for (int nt = 0; nt < 16; nt++) {
        const int gc = F0 + nt * 8 + 2 * c;
        *(float2*)(g_h + (size_t)gr0 * OUT_ + gc)       = make_float2(acc[nt][0], acc[nt][1]);
        *(float2*)(g_h + (size_t)(gr0 + 8) * OUT_ + gc) = make_float2(acc[nt][2], acc[nt][3]);
    }

    const int b = gr0 >> 10;
    const int n = gr0 & (N_ - 1);
#pragma unroll
    for (int hh = 0; hh < 2; hh++) {
        float ps0 = 0.f, ps1 = 0.f, pd0 = 0.f, pd1 = 0.f;
#pragma unroll
        for (int t = 0; t < 8; t++) {
            const int nt = hh * 8 + t;
            const int gc = F0 + nt * 8 + 2 * c;
            float2 as2 = *(float2*)&sAs[gc];
            float2 ad2 = *(float2*)&sAd[gc];
            ps0 += acc[nt][0] * as2.x + acc[nt][1] * as2.y;
            ps1 += acc[nt][2] * as2.x + acc[nt][3] * as2.y;
            pd0 += acc[nt][0] * ad2.x + acc[nt][1] * ad2.y;
            pd1 += acc[nt][2] * ad2.x + acc[nt][3] * ad2.y;
        }
#pragma unroll
        for (int off = 1; off <= 2; off <<= 1) {
            ps0 += __shfl_xor_sync(0xffffffffu, ps0, off);
            ps1 += __shfl_xor_sync(0xffffffffu, ps1, off);
            pd0 += __shfl_xor_sync(0xffffffffu, pd0, off);
            pd1 += __shfl_xor_sync(0xffffffffu, pd1, off);
        }
        if (c == 0) {
            const int hd = blockIdx.y * 2 + hh;
            g_esrc[(b * H_ + hd) * N_ + n]     = ps0;
            g_esrc[(b * H_ + hd) * N_ + n + 8] = ps1;
            g_edst[(b * H_ + hd) * N_ + n]     = pd0;
            g_edst[(b * H_ + hd) * N_ + n + 8] = pd1;
        }
    }
}

// ============================================================================
// Kernel 1b: transpose + split + pack h -> g_hTi (unchanged from R13).
// ============================================================================
__global__ __launch_bounds__(256) void transpose_pack_kernel()
{
    __shared__ float h_t[64 * 65];

    const int bid = blockIdx.x;
    const int hd  = bid & 3;
    const int jb  = (bid >> 2) & 15;
    const int b   = bid >> 6;
    const int tid = threadIdx.x;

    for (int idx = tid; idx < 1024; idx += 256) {
        int j  = idx >> 4;
        int f4 = idx & 15;
        float4 v = *(const float4*)(g_h + (size_t)(b * N_ + jb * 64 + j) * OUT_ + hd * 64 + f4 * 4);
        h_t[(f4 * 4 + 0) * 65 + j] = v.x;
        h_t[(f4 * 4 + 1) * 65 + j] = v.y;
        h_t[(f4 * 4 + 2) * 65 + j] = v.z;
        h_t[(f4 * 4 + 3) * 65 + j] = v.w;
    }
    __syncthreads();

    const int chunk = jb >> 1;
    const int half  = jb & 1;
    uint4* gt = g_hTi + ((size_t)((b * H_ + hd) * 8 + chunk)) * 2048;

    const int f = tid >> 2;
#pragma unroll
    for (int v = 0; v < 4; v++) {
        const int colL = (tid & 3) * 4 + v;
        const int ktL  = colL >> 2;
        const int cc   = colL & 3;
        const int jL   = ktL * 16 + 2 * cc;
        float a0 = h_t[f * 65 + jL];
        float a1 = h_t[f * 65 + jL + 1];
        float a2 = h_t[f * 65 + jL + 8];
        float a3 = h_t[f * 65 + jL + 9];
        gt[f * 32 + half * 16 + colL] =
            make_uint4(hi_pack(a0, a1), hi_pack(a2, a3),
                       lo_pack(a0, a1), lo_pack(a2, a3));
    }
}

// ============================================================================
// Kernel 2: HMMA flash-GAT, ONE head per CTA for occupancy (3 CTAs/SM).
// CTA = (b, 128 i-rows, 1 head); grid (8, 16, 4); 8 warps.
// Adjacency ballots kept in registers (warp-private rows) — no abits smem.
// e_dst kept in registers. smem = es (512B) + hbi (36 KB).
// ============================================================================
#define HBI_STR 36

__global__ __launch_bounds__(256, 3) void gat_attn_mma_kernel(
    const float* __restrict__ adj, const float* __restrict__ bias,
    float* __restrict__ out)
{
    __shared__ float es_sh[128];
    __shared__ __align__(16) uint4 hbi[64 * HBI_STR];

    const int tid = threadIdx.x;
    const int wid = tid >> 5;
    const int l   = tid & 31;
    const int q   = l >> 2;
    const int c   = l & 3;
    const int b   = blockIdx.y;
    const int i0  = blockIdx.x * 128;
    const int hd  = blockIdx.z;

    const int r0 = wid * 16 + q;
    const float ed0 = g_edst[(b * H_ + hd) * N_ + i0 + r0];
    const float ed1 = g_edst[(b * H_ + hd) * N_ + i0 + r0 + 8];

    float acc[8][4];
    float den0 = 0.f, den1 = 0.f;
#pragma unroll
    for (int nt = 0; nt < 8; nt++)
#pragma unroll
        for (int k = 0; k < 4; k++) acc[nt][k] = 0.f;

    const float* adj_b = adj + (size_t)b * N_ * N_;

    for (int chunk = 0; chunk < 8; chunk++) {
        const int j0 = chunk * 128;
        __syncthreads();   // previous es/hbi reads complete

        // adjacency ballots -> registers (warp-private rows wid*16..+15)
        uint32_t wr0[4], wr1[4];
#pragma unroll 4
        for (int k = 0; k < 16; k++) {
            const float* arow = adj_b + (size_t)(i0 + wid * 16 + k) * N_ + j0;
#pragma unroll
            for (int jg = 0; jg < 4; jg++) {
                uint32_t m = __ballot_sync(0xffffffffu, arow[jg * 32 + l] > 0.5f);
                if (k == q)     wr0[jg] = m;
                if (k == q + 8) wr1[jg] = m;
            }
        }
        if (tid < 128)
            es_sh[tid] = g_esrc[(b * H_ + hd) * N_ + j0 + tid];
        // stage packed B fragments: pure copy, coalesced src, CF dst
        {
            const uint4* gt = g_hTi + ((size_t)((b * H_ + hd) * 8 + chunk)) * 2048;
#pragma unroll
            for (int v = 0; v < 8; v++) {
                int idx = tid + v * 256;
                int f = idx >> 5, col = idx & 31;
                hbi[f * HBI_STR + col] = gt[idx];
            }
        }
        __syncthreads();

        float dsum0 = 0.f, dsum1 = 0.f;
#pragma unroll
        for (int kt = 0; kt < 8; kt++) {
            const int jA = kt * 16 + c * 2;
            float2 eA = *(const float2*)&es_sh[jA];
            float2 eB = *(const float2*)&es_sh[jA + 8];
            const uint32_t w0 = wr0[kt >> 1];
            const uint32_t w1 = wr1[kt >> 1];
            const int bb = ((kt & 1) << 4) + c * 2;

            float p00, p01, p08, p09, p10, p11, p18, p19;
            {
                float s;
                s = ed0 + eA.x; s = fmaxf(s, 0.2f * s); p00 = ((w0 >> bb) & 1u) ? __expf(s) : 0.f;
                s = ed0 + eA.y; s = fmaxf(s, 0.2f * s); p01 = ((w0 >> (bb + 1)) & 1u) ? __expf(s) : 0.f;
                s = ed0 + eB.x; s = fmaxf(s, 0.2f * s); p08 = ((w0 >> (bb + 8)) & 1u) ? __expf(s) : 0.f;
                s = ed0 + eB.y; s = fmaxf(s, 0.2f * s); p09 = ((w0 >> (bb + 9)) & 1u) ? __expf(s) : 0.f;
                s = ed1 + eA.x; s = fmaxf(s, 0.2f * s); p10 = ((w1 >> bb) & 1u) ? __expf(s) : 0.f;
                s = ed1 + eA.y; s = fmaxf(s, 0.2f * s); p11 = ((w1 >> (bb + 1)) & 1u) ? __expf(s) : 0.f;
                s = ed1 + eB.x; s = fmaxf(s, 0.2f * s); p18 = ((w1 >> (bb + 8)) & 1u) ? __expf(s) : 0.f;
                s = ed1 + eB.y; s = fmaxf(s, 0.2f * s); p19 = ((w1 >> (bb + 9)) & 1u) ? __expf(s) : 0.f;
            }
            dsum0 += (p00 + p01) + (p08 + p09);
            dsum1 += (p10 + p11) + (p18 + p19);

            const uint32_t a0h = hi_pack(p00, p01), a1h = hi_pack(p10, p11);
            const uint32_t a2h = hi_pack(p08, p09), a3h = hi_pack(p18, p19);
            const uint32_t a0l = lo_pack(p00, p01), a1l = lo_pack(p10, p11);
            const uint32_t a2l = lo_pack(p08, p09), a3l = lo_pack(p18, p19);

#pragma unroll
            for (int nt = 0; nt < 8; nt++) {
                uint4 v = hbi[(nt * 8 + q) * HBI_STR + kt * 4 + c];
                mma16816(acc[nt], a0h, a1h, a2h, a3h, v.x, v.y);
                mma16816(acc[nt], a0h, a1h, a2h, a3h, v.z, v.w);
                mma16816(acc[nt], a0l, a1l, a2l, a3l, v.x, v.y);
            }
        }
        den0 += dsum0;
        den1 += dsum1;
    }

    // ---- epilogue: out = acc / den + bias ----
    den0 += __shfl_xor_sync(0xffffffffu, den0, 1);
    den0 += __shfl_xor_sync(0xffffffffu, den0, 2);
    den1 += __shfl_xor_sync(0xffffffffu, den1, 1);
    den1 += __shfl_xor_sync(0xffffffffu, den1, 2);
    const float rl0 = 1.0f / den0, rl1 = 1.0f / den1;

    const int gr0 = b * N_ + i0 + r0;
#pragma unroll
    for (int nt = 0; nt < 8; nt++) {
        const int col = hd * 64 + nt * 8 + c * 2;
        float2 bv = __ldg((const float2*)(bias + col));
        float2 o0, o1;
        o0.x = acc[nt][0] * rl0 + bv.x;
        o0.y = acc[nt][1] * rl0 + bv.y;
        o1.x = acc[nt][2] * rl1 + bv.x;
        o1.y = acc[nt][3] * rl1 + bv.y;
        *(float2*)(out + (size_t)gr0 * OUT_ + col)       = o0;
        *(float2*)(out + (size_t)(gr0 + 8) * OUT_ + col) = o1;
    }
}

// ============================================================================
extern "C" void kernel_launch(void* const* d_in, const int* in_sizes, int n_in,
                              void* d_out, int out_size)
{
    const float* x     = (const float*)d_in[0];
    const float* adj   = (const float*)d_in[1];
    const float* W     = (const float*)d_in[2];
    const float* a_src = (const float*)d_in[3];
    const float* a_dst = (const float*)d_in[4];
    const float* bias  = (const float*)d_in[5];
    float* out = (float*)d_out;

    gemm_h_mma_kernel<<<dim3((B_ * N_) / 128, 2), 256>>>(x, W, a_src, a_dst);
    transpose_pack_kernel<<<B_ * 16 * H_, 256>>>();
    gat_attn_mma_kernel<<<dim3(N_ / 128, B_, H_), 256>>>(adj, bias, out);
}

// round 15
// speedup vs baseline: 1.0015x; 1.0015x over previous
#include <cuda_runtime.h>
#include <cuda_bf16.h>
#include <cstdint>

#define B_   16
#define N_   1024
#define DIN_ 256
#define H_   4
#define F_   64
#define OUT_ 256

// -------- scratch (device globals) --------
__device__ float g_h[B_ * N_ * OUT_];        // h fp32 row-major
__device__ float g_esrc[B_ * H_ * N_];
__device__ float g_edst[B_ * H_ * N_];
// Interleaved B-fragment tiles, f-major: per (b, hd, chunk): gt[f*32 + col],
// col = kt*4+cc (j0 = chunk*128 + kt*16 + 2cc), uint4 =
// {hi(j0,j0+1), hi(j0+8,j0+9), lo(j0,j0+1), lo(j0+8,j0+9)}.
__device__ uint4 g_hTi[B_ * H_ * 8 * 2048];

// bf16 split helpers
__device__ __forceinline__ uint32_t hi_pack(float v0, float v1) {
    uint32_t r;
    asm("prmt.b32 %0, %1, %2, 0x7632;" : "=r"(r)
        : "r"(__float_as_uint(v0)), "r"(__float_as_uint(v1)));
    return r;
}
__device__ __forceinline__ uint32_t lo_pack(float v0, float v1) {
    float l0 = v0 - __uint_as_float(__float_as_uint(v0) & 0xFFFF0000u);
    float l1 = v1 - __uint_as_float(__float_as_uint(v1) & 0xFFFF0000u);
    uint32_t r;
    asm("cvt.rn.bf16x2.f32 %0, %1, %2;" : "=r"(r) : "f"(l1), "f"(l0));
    return r;
}

// warp-level bf16 MMA (HMMA path, sm_80+)
__device__ __forceinline__ void mma16816(float* c, uint32_t a0, uint32_t a1,
                                         uint32_t a2, uint32_t a3,
                                         uint32_t b0, uint32_t b1) {
    asm volatile(
        "mma.sync.aligned.m16n8k16.row.col.f32.bf16.bf16.f32 "
        "{%0,%1,%2,%3}, {%4,%5,%6,%7}, {%8,%9}, {%0,%1,%2,%3};"
        : "+f"(c[0]), "+f"(c[1]), "+f"(c[2]), "+f"(c[3])
        : "r"(a0), "r"(a1), "r"(a2), "r"(a3), "r"(b0), "r"(b1));
}

// ============================================================================
// Kernel 1: h = x @ W via split-bf16 HMMA, double-buffered smem stages
// (R14 version, measured 36.3 us).
// ============================================================================
__global__ __launch_bounds__(256, 2) void gemm_h_mma_kernel(
    const float* __restrict__ x, const float* __restrict__ W,
    const float* __restrict__ a_src, const float* __restrict__ a_dst)
{
    __shared__ uint32_t sxh[2][128 * 12];
    __shared__ uint32_t sxl[2][128 * 12];
    __shared__ uint4    swt[2][128 * 4];
    __shared__ float    sAs[256];
    __shared__ float    sAd[256];

    const int tid = threadIdx.x;
    const int wid = tid >> 5;
    const int l   = tid & 31;
    const int q   = l >> 2;
    const int c   = l & 3;
    const int R0  = blockIdx.x * 128;
    const int F0  = blockIdx.y * 128;

    sAs[tid] = a_src[tid];
    sAd[tid] = a_dst[tid];

    float acc[16][4];
#pragma unroll
    for (int nt = 0; nt < 16; nt++)
#pragma unroll
        for (int k = 0; k < 4; k++) acc[nt][k] = 0.f;

    const int xr = tid >> 1, xh = tid & 1;
    const int wf = tid >> 1, wh = tid & 1;

    float4 pxa, pxb;
    float  pw[2][4];

    {   // load kt = 0 into regs
        const float* xp = x + (size_t)(R0 + xr) * DIN_ + xh * 8;
        pxa = *(const float4*)xp;
        pxb = *(const float4*)(xp + 4);
#pragma unroll
        for (int t = 0; t < 2; t++) {
            int cc = wh * 2 + t;
            const float* wp = W + (size_t)(2 * cc) * OUT_ + F0 + wf;
            pw[t][0] = wp[0]; pw[t][1] = wp[OUT_];
            pw[t][2] = wp[8 * OUT_]; pw[t][3] = wp[9 * OUT_];
        }
    }
    {   // store kt = 0 into buf 0
        *(uint4*)&sxh[0][xr * 12 + xh * 4] =
            make_uint4(hi_pack(pxa.x, pxa.y), hi_pack(pxa.z, pxa.w),
                       hi_pack(pxb.x, pxb.y), hi_pack(pxb.z, pxb.w));
        *(uint4*)&sxl[0][xr * 12 + xh * 4] =
            make_uint4(lo_pack(pxa.x, pxa.y), lo_pack(pxa.z, pxa.w),
                       lo_pack(pxb.x, pxb.y), lo_pack(pxb.z, pxb.w));
#pragma unroll
        for (int t = 0; t < 2; t++) {
            int cc = wh * 2 + t;
            swt[0][wf * 4 + cc] =
                make_uint4(hi_pack(pw[t][0], pw[t][1]), hi_pack(pw[t][2], pw[t][3]),
                           lo_pack(pw[t][0], pw[t][1]), lo_pack(pw[t][2], pw[t][3]));
        }
    }
    __syncthreads();

    for (int kt = 0; kt < 16; kt++) {
        const int cur = kt & 1, nxt = cur ^ 1;
        if (kt < 15) {
            const float* xp = x + (size_t)(R0 + xr) * DIN_ + (kt + 1) * 16 + xh * 8;
            pxa = *(const float4*)xp;
            pxb = *(const float4*)(xp + 4);
#pragma unroll
            for (int t = 0; t < 2; t++) {
                int cc = wh * 2 + t;
                const float* wp = W + (size_t)((kt + 1) * 16 + 2 * cc) * OUT_ + F0 + wf;
                pw[t][0] = wp[0]; pw[t][1] = wp[OUT_];
                pw[t][2] = wp[8 * OUT_]; pw[t][3] = wp[9 * OUT_];
            }
        }

        const int r0 = wid * 16 + q;
        const uint32_t ah0 = sxh[cur][r0 * 12 + c];
        const uint32_t ah1 = sxh[cur][(r0 + 8) * 12 + c];
        const uint32_t ah2 = sxh[cur][r0 * 12 + c + 4];
        const uint32_t ah3 = sxh[cur][(r0 + 8) * 12 + c + 4];
        const uint32_t al0 = sxl[cur][r0 * 12 + c];
        const uint32_t al1 = sxl[cur][(r0 + 8) * 12 + c];
        const uint32_t al2 = sxl[cur][r0 * 12 + c + 4];
        const uint32_t al3 = sxl[cur][(r0 + 8) * 12 + c + 4];

#pragma unroll
        for (int nt = 0; nt < 16; nt++) {
            uint4 v = swt[cur][(nt * 8 + q) * 4 + c];
            mma16816(acc[nt], ah0, ah1, ah2, ah3, v.x, v.y);
            mma16816(acc[nt], ah0, ah1, ah2, ah3, v.z, v.w);
            mma16816(acc[nt], al0, al1, al2, al3, v.x, v.y);
        }

        if (kt < 15) {
            *(uint4*)&sxh[nxt][xr * 12 + xh * 4] =
                make_uint4(hi_pack(pxa.x, pxa.y), hi_pack(pxa.z, pxa.w),
                           hi_pack(pxb.x, pxb.y), hi_pack(pxb.z, pxb.w));
            *(uint4*)&sxl[nxt][xr * 12 + xh * 4] =
                make_uint4(lo_pack(pxa.x, pxa.y), lo_pack(pxa.z, pxa.w),
                           lo_pack(pxb.x, pxb.y), lo_pack(pxb.z, pxb.w));
#pragma unroll
            for (int t = 0; t < 2; t++) {
                int cc = wh * 2 + t;
                swt[nxt][wf * 4 + cc] =
                    make_uint4(hi_pack(pw[t][0], pw[t][1]), hi_pack(pw[t][2], pw[t][3]),
                               lo_pack(pw[t][0], pw[t][1]), lo_pack(pw[t][2], pw[t][3]));
            }
            __syncthreads();
        }
    }

    // ---- epilogue: store h fp32 + e_src/e_dst reductions ----
    const int gr0 = R0 + wid * 16 + q;
#pragma unroll
    for (int nt = 0; nt < 16; nt++) {
        const int gc = F0 + nt * 8 + 2 * c;
        *(float2*)(g_h + (size_t)gr0 * OUT_ + gc)       = make_float2(acc[nt][0], acc[nt][1]);
        *(float2*)(g_h + (size_t)(gr0 + 8) * OUT_ + gc) = make_float2(acc[nt][2], acc[nt][3]);
    }

    const int b = gr0 >> 10;
    const int n = gr0 & (N_ - 1);
#pragma unroll
    for (int hh = 0; hh < 2; hh++) {
        float ps0 = 0.f, ps1 = 0.f, pd0 = 0.f, pd1 = 0.f;
#pragma unroll
        for (int t = 0; t < 8; t++) {
            const int nt = hh * 8 + t;
            const int gc = F0 + nt * 8 + 2 * c;
            float2 as2 = *(float2*)&sAs[gc];
            float2 ad2 = *(float2*)&sAd[gc];
            ps0 += acc[nt][0] * as2.x + acc[nt][1] * as2.y;
            ps1 += acc[nt][2] * as2.x + acc[nt][3] * as2.y;
            pd0 += acc[nt][0] * ad2.x + acc[nt][1] * ad2.y;
            pd1 += acc[nt][2] * ad2.x + acc[nt][3] * ad2.y;
        }
#pragma unroll
        for (int off = 1; off <= 2; off <<= 1) {
            ps0 += __shfl_xor_sync(0xffffffffu, ps0, off);
            ps1 += __shfl_xor_sync(0xffffffffu, ps1, off);
            pd0 += __shfl_xor_sync(0xffffffffu, pd0, off);
            pd1 += __shfl_xor_sync(0xffffffffu, pd1, off);
        }
        if (c == 0) {
            const int hd = blockIdx.y * 2 + hh;
            g_esrc[(b * H_ + hd) * N_ + n]     = ps0;
            g_esrc[(b * H_ + hd) * N_ + n + 8] = ps1;
            g_edst[(b * H_ + hd) * N_ + n]     = pd0;
            g_edst[(b * H_ + hd) * N_ + n + 8] = pd1;
        }
    }
}

// ============================================================================
// Kernel 1b: transpose + split + pack h -> g_hTi (unchanged from R13).
// ============================================================================
__global__ __launch_bounds__(256) void transpose_pack_kernel()
{
    __shared__ float h_t[64 * 65];

    const int bid = blockIdx.x;
    const int hd  = bid & 3;
    const int jb  = (bid >> 2) & 15;
    const int b   = bid >> 6;
    const int tid = threadIdx.x;

    for (int idx = tid; idx < 1024; idx += 256) {
        int j  = idx >> 4;
        int f4 = idx & 15;
        float4 v = *(const float4*)(g_h + (size_t)(b * N_ + jb * 64 + j) * OUT_ + hd * 64 + f4 * 4);
        h_t[(f4 * 4 + 0) * 65 + j] = v.x;
        h_t[(f4 * 4 + 1) * 65 + j] = v.y;
        h_t[(f4 * 4 + 2) * 65 + j] = v.z;
        h_t[(f4 * 4 + 3) * 65 + j] = v.w;
    }
    __syncthreads();

    const int chunk = jb >> 1;
    const int half  = jb & 1;
    uint4* gt = g_hTi + ((size_t)((b * H_ + hd) * 8 + chunk)) * 2048;

    const int f = tid >> 2;
#pragma unroll
    for (int v = 0; v < 4; v++) {
        const int colL = (tid & 3) * 4 + v;
        const int ktL  = colL >> 2;
        const int cc   = colL & 3;
        const int jL   = ktL * 16 + 2 * cc;
        float a0 = h_t[f * 65 + jL];
        float a1 = h_t[f * 65 + jL + 1];
        float a2 = h_t[f * 65 + jL + 8];
        float a3 = h_t[f * 65 + jL + 9];
        gt[f * 32 + half * 16 + colL] =
            make_uint4(hi_pack(a0, a1), hi_pack(a2, a3),
                       lo_pack(a0, a1), lo_pack(a2, a3));
    }
}

// ============================================================================
// Kernel 2: HMMA flash-GAT (R13 2-head structure, measured ~138 us), with
// adjacency ballots kept in REGISTERS (warp-private rows; no abits smem).
// CTA = (b, 128 i-rows, 2 heads); grid.z = 2; 8 warps.
// ============================================================================
#define HBI_STR 36

__global__ __launch_bounds__(256, 2) void gat_attn_mma_kernel(
    const float* __restrict__ adj, const float* __restrict__ bias,
    float* __restrict__ out)
{
    __shared__ float es_sh[2][128];
    __shared__ float ed_sh[2][128];
    __shared__ __align__(16) uint4 hbi[64 * HBI_STR];

    const int tid = threadIdx.x;
    const int wid = tid >> 5;
    const int l   = tid & 31;
    const int q   = l >> 2;
    const int c   = l & 3;
    const int b   = blockIdx.y;
    const int i0  = blockIdx.x * 128;
    const int hp  = blockIdx.z;          // head pair: heads hp*2, hp*2+1

    for (int idx = tid; idx < 2 * 128; idx += 256)
        ed_sh[idx >> 7][idx & 127] =
            g_edst[(b * H_ + hp * 2 + (idx >> 7)) * N_ + i0 + (idx & 127)];

    float acc[2][8][4];
    float den[2][2];
#pragma unroll
    for (int hh = 0; hh < 2; hh++) {
        den[hh][0] = 0.f; den[hh][1] = 0.f;
#pragma unroll
        for (int nt = 0; nt < 8; nt++)
#pragma unroll
            for (int k = 0; k < 4; k++) acc[hh][nt][k] = 0.f;
    }

    const float* adj_b = adj + (size_t)b * N_ * N_;

    for (int chunk = 0; chunk < 8; chunk++) {
        const int j0 = chunk * 128;

        // adjacency ballots -> registers (warp-private rows wid*16..+15)
        uint32_t wr0[4], wr1[4];
#pragma unroll 4
        for (int k = 0; k < 16; k++) {
            const float* arow = adj_b + (size_t)(i0 + wid * 16 + k) * N_ + j0;
#pragma unroll
            for (int jg = 0; jg < 4; jg++) {
                uint32_t m = __ballot_sync(0xffffffffu, arow[jg * 32 + l] > 0.5f);
                if (k == q)     wr0[jg] = m;
                if (k == q + 8) wr1[jg] = m;
            }
        }
        __syncthreads();   // prev es/hbi reads done before overwrite
        for (int idx = tid; idx < 2 * 128; idx += 256)
            es_sh[idx >> 7][idx & 127] =
                g_esrc[(b * H_ + hp * 2 + (idx >> 7)) * N_ + j0 + (idx & 127)];

#pragma unroll
        for (int hh = 0; hh < 2; hh++) {
            if (hh == 1) __syncthreads();   // prev head's hbi reads done
            // stage packed B fragments: pure copy, coalesced src, CF dst
            {
                const uint4* gt = g_hTi +
                    ((size_t)((b * H_ + hp * 2 + hh) * 8 + chunk)) * 2048;
#pragma unroll
                for (int v = 0; v < 8; v++) {
                    int idx = tid + v * 256;
                    int f = idx >> 5, col = idx & 31;
                    hbi[f * HBI_STR + col] = gt[idx];
                }
            }
            __syncthreads();

            const int r0 = wid * 16 + q;
            const float ed0 = ed_sh[hh][r0];
            const float ed1 = ed_sh[hh][r0 + 8];
            float dsum0 = 0.f, dsum1 = 0.f;
#pragma unroll
            for (int kt = 0; kt < 8; kt++) {
                const int jA = kt * 16 + c * 2;
                float2 eA = *(const float2*)&es_sh[hh][jA];
                float2 eB = *(const float2*)&es_sh[hh][jA + 8];
                const uint32_t w0 = wr0[kt >> 1];
                const uint32_t w1 = wr1[kt >> 1];
                const int bb = ((kt & 1) << 4) + c * 2;

                float p00, p01, p08, p09, p10, p11, p18, p19;
                {
                    float s;
                    s = ed0 + eA.x; s = fmaxf(s, 0.2f * s); p00 = ((w0 >> bb) & 1u) ? __expf(s) : 0.f;
                    s = ed0 + eA.y; s = fmaxf(s, 0.2f * s); p01 = ((w0 >> (bb + 1)) & 1u) ? __expf(s) : 0.f;
                    s = ed0 + eB.x; s = fmaxf(s, 0.2f * s); p08 = ((w0 >> (bb + 8)) & 1u) ? __expf(s) : 0.f;
                    s = ed0 + eB.y; s = fmaxf(s, 0.2f * s); p09 = ((w0 >> (bb + 9)) & 1u) ? __expf(s) : 0.f;
                    s = ed1 + eA.x; s = fmaxf(s, 0.2f * s); p10 = ((w1 >> bb) & 1u) ? __expf(s) : 0.f;
                    s = ed1 + eA.y; s = fmaxf(s, 0.2f * s); p11 = ((w1 >> (bb + 1)) & 1u) ? __expf(s) : 0.f;
                    s = ed1 + eB.x; s = fmaxf(s, 0.2f * s); p18 = ((w1 >> (bb + 8)) & 1u) ? __expf(s) : 0.f;
                    s = ed1 + eB.y; s = fmaxf(s, 0.2f * s); p19 = ((w1 >> (bb + 9)) & 1u) ? __expf(s) : 0.f;
                }
                dsum0 += (p00 + p01) + (p08 + p09);
                dsum1 += (p10 + p11) + (p18 + p19);

                const uint32_t a0h = hi_pack(p00, p01), a1h = hi_pack(p10, p11);
                const uint32_t a2h = hi_pack(p08, p09), a3h = hi_pack(p18, p19);
                const uint32_t a0l = lo_pack(p00, p01), a1l = lo_pack(p10, p11);
                const uint32_t a2l = lo_pack(p08, p09), a3l = lo_pack(p18, p19);

#pragma unroll
                for (int nt = 0; nt < 8; nt++) {
                    uint4 v = hbi[(nt * 8 + q) * HBI_STR + kt * 4 + c];
                    mma16816(acc[hh][nt], a0h, a1h, a2h, a3h, v.x, v.y);
                    mma16816(acc[hh][nt], a0h, a1h, a2h, a3h, v.z, v.w);
                    mma16816(acc[hh][nt], a0l, a1l, a2l, a3l, v.x, v.y);
                }
            }
            den[hh][0] += dsum0;
            den[hh][1] += dsum1;
        }
    }

    // ---- epilogue: out = acc / den + bias ----
    const int gr0 = b * N_ + i0 + wid * 16 + q;
#pragma unroll
    for (int hh = 0; hh < 2; hh++) {
        float d0 = den[hh][0];
        d0 += __shfl_xor_sync(0xffffffffu, d0, 1);
        d0 += __shfl_xor_sync(0xffffffffu, d0, 2);
        float d1 = den[hh][1];
        d1 += __shfl_xor_sync(0xffffffffu, d1, 1);
        d1 += __shfl_xor_sync(0xffffffffu, d1, 2);
        const float rl0 = 1.0f / d0, rl1 = 1.0f / d1;
#pragma unroll
        for (int nt = 0; nt < 8; nt++) {
            const int col = (hp * 2 + hh) * 64 + nt * 8 + c * 2;
            float2 bv = __ldg((const float2*)(bias + col));
            float2 o0, o1;
            o0.x = acc[hh][nt][0] * rl0 + bv.x;
            o0.y = acc[hh][nt][1] * rl0 + bv.y;
            o1.x = acc[hh][nt][2] * rl1 + bv.x;
            o1.y = acc[hh][nt][3] * rl1 + bv.y;
            *(float2*)(out + (size_t)gr0 * OUT_ + col)       = o0;
            *(float2*)(out + (size_t)(gr0 + 8) * OUT_ + col) = o1;
        }
    }
}

// ============================================================================
extern "C" void kernel_launch(void* const* d_in, const int* in_sizes, int n_in,
                              void* d_out, int out_size)
{
    const float* x     = (const float*)d_in[0];
    const float* adj   = (const float*)d_in[1];
    const float* W     = (const float*)d_in[2];
    const float* a_src = (const float*)d_in[3];
    const float* a_dst = (const float*)d_in[4];
    const float* bias  = (const float*)d_in[5];
    float* out = (float*)d_out;

    gemm_h_mma_kernel<<<dim3((B_ * N_) / 128, 2), 256>>>(x, W, a_src, a_dst);
    transpose_pack_kernel<<<B_ * 16 * H_, 256>>>();
    gat_attn_mma_kernel<<<dim3(N_ / 128, B_, 2), 256>>>(adj, bias, out);
}

// round 16
// speedup vs baseline: 1.1837x; 1.1820x over previous
#include <cuda_runtime.h>
#include <cuda_bf16.h>
#include <cstdint>

#define B_   16
#define N_   1024
#define DIN_ 256
#define H_   4
#define F_   64
#define OUT_ 256

// -------- scratch (device globals) --------
__device__ float g_h[B_ * N_ * OUT_];        // h fp32 row-major
__device__ float g_esrc[B_ * H_ * N_];
__device__ float g_edst[B_ * H_ * N_];
// Interleaved B-fragment tiles, f-major: per (b, hd, chunk): gt[f*32 + col],
// col = kt*4+cc (j0 = chunk*128 + kt*16 + 2cc), uint4 =
// {hi(j0,j0+1), hi(j0+8,j0+9), lo(j0,j0+1), lo(j0+8,j0+9)}.
__device__ uint4 g_hTi[B_ * H_ * 8 * 2048];

// bf16 split helpers
__device__ __forceinline__ uint32_t hi_pack(float v0, float v1) {
    uint32_t r;
    asm("prmt.b32 %0, %1, %2, 0x7632;" : "=r"(r)
        : "r"(__float_as_uint(v0)), "r"(__float_as_uint(v1)));
    return r;
}
__device__ __forceinline__ uint32_t lo_pack(float v0, float v1) {
    float l0 = v0 - __uint_as_float(__float_as_uint(v0) & 0xFFFF0000u);
    float l1 = v1 - __uint_as_float(__float_as_uint(v1) & 0xFFFF0000u);
    uint32_t r;
    asm("cvt.rn.bf16x2.f32 %0, %1, %2;" : "=r"(r) : "f"(l1), "f"(l0));
    return r;
}

// warp-level bf16 MMA (HMMA path, sm_80+)
__device__ __forceinline__ void mma16816(float* c, uint32_t a0, uint32_t a1,
                                         uint32_t a2, uint32_t a3,
                                         uint32_t b0, uint32_t b1) {
    asm volatile(
        "mma.sync.aligned.m16n8k16.row.col.f32.bf16.bf16.f32 "
        "{%0,%1,%2,%3}, {%4,%5,%6,%7}, {%8,%9}, {%0,%1,%2,%3};"
        : "+f"(c[0]), "+f"(c[1]), "+f"(c[2]), "+f"(c[3])
        : "r"(a0), "r"(a1), "r"(a2), "r"(a3), "r"(b0), "r"(b1));
}

// ============================================================================
// Kernel 1: h = x @ W via split-bf16 HMMA, double-buffered smem stages
// (R14 version, measured 36.0-36.3 us).
// ============================================================================
__global__ __launch_bounds__(256, 2) void gemm_h_mma_kernel(
    const float* __restrict__ x, const float* __restrict__ W,
    const float* __restrict__ a_src, const float* __restrict__ a_dst)
{
    __shared__ uint32_t sxh[2][128 * 12];
    __shared__ uint32_t sxl[2][128 * 12];
    __shared__ uint4    swt[2][128 * 4];
    __shared__ float    sAs[256];
    __shared__ float    sAd[256];

    const int tid = threadIdx.x;
    const int wid = tid >> 5;
    const int l   = tid & 31;
    const int q   = l >> 2;
    const int c   = l & 3;
    const int R0  = blockIdx.x * 128;
    const int F0  = blockIdx.y * 128;

    sAs[tid] = a_src[tid];
    sAd[tid] = a_dst[tid];

    float acc[16][4];
#pragma unroll
    for (int nt = 0; nt < 16; nt++)
#pragma unroll
        for (int k = 0; k < 4; k++) acc[nt][k] = 0.f;

    const int xr = tid >> 1, xh = tid & 1;
    const int wf = tid >> 1, wh = tid & 1;

    float4 pxa, pxb;
    float  pw[2][4];

    {   // load kt = 0 into regs
        const float* xp = x + (size_t)(R0 + xr) * DIN_ + xh * 8;
        pxa = *(const float4*)xp;
        pxb = *(const float4*)(xp + 4);
#pragma unroll
        for (int t = 0; t < 2; t++) {
            int cc = wh * 2 + t;
            const float* wp = W + (size_t)(2 * cc) * OUT_ + F0 + wf;
            pw[t][0] = wp[0]; pw[t][1] = wp[OUT_];
            pw[t][2] = wp[8 * OUT_]; pw[t][3] = wp[9 * OUT_];
        }
    }
    {   // store kt = 0 into buf 0
        *(uint4*)&sxh[0][xr * 12 + xh * 4] =
            make_uint4(hi_pack(pxa.x, pxa.y), hi_pack(pxa.z, pxa.w),
                       hi_pack(pxb.x, pxb.y), hi_pack(pxb.z, pxb.w));
        *(uint4*)&sxl[0][xr * 12 + xh * 4] =
            make_uint4(lo_pack(pxa.x, pxa.y), lo_pack(pxa.z, pxa.w),
                       lo_pack(pxb.x, pxb.y), lo_pack(pxb.z, pxb.w));
#pragma unroll
        for (int t = 0; t < 2; t++) {
            int cc = wh * 2 + t;
            swt[0][wf * 4 + cc] =
                make_uint4(hi_pack(pw[t][0], pw[t][1]), hi_pack(pw[t][2], pw[t][3]),
                           lo_pack(pw[t][0], pw[t][1]), lo_pack(pw[t][2], pw[t][3]));
        }
    }
    __syncthreads();

    for (int kt = 0; kt < 16; kt++) {
        const int cur = kt & 1, nxt = cur ^ 1;
        if (kt < 15) {
            const float* xp = x + (size_t)(R0 + xr) * DIN_ + (kt + 1) * 16 + xh * 8;
            pxa = *(const float4*)xp;
            pxb = *(const float4*)(xp + 4);
#pragma unroll
            for (int t = 0; t < 2; t++) {
                int cc = wh * 2 + t;
                const float* wp = W + (size_t)((kt + 1) * 16 + 2 * cc) * OUT_ + F0 + wf;
                pw[t][0] = wp[0]; pw[t][1] = wp[OUT_];
                pw[t][2] = wp[8 * OUT_]; pw[t][3] = wp[9 * OUT_];
            }
        }

        const int r0 = wid * 16 + q;
        const uint32_t ah0 = sxh[cur][r0 * 12 + c];
        const uint32_t ah1 = sxh[cur][(r0 + 8) * 12 + c];
        const uint32_t ah2 = sxh[cur][r0 * 12 + c + 4];
        const uint32_t ah3 = sxh[cur][(r0 + 8) * 12 + c + 4];
        const uint32_t al0 = sxl[cur][r0 * 12 + c];
        const uint32_t al1 = sxl[cur][(r0 + 8) * 12 + c];
        const uint32_t al2 = sxl[cur][r0 * 12 + c + 4];
        const uint32_t al3 = sxl[cur][(r0 + 8) * 12 + c + 4];

#pragma unroll
        for (int nt = 0; nt < 16; nt++) {
            uint4 v = swt[cur][(nt * 8 + q) * 4 + c];
            mma16816(acc[nt], ah0, ah1, ah2, ah3, v.x, v.y);
            mma16816(acc[nt], ah0, ah1, ah2, ah3, v.z, v.w);
            mma16816(acc[nt], al0, al1, al2, al3, v.x, v.y);
        }

        if (kt < 15) {
            *(uint4*)&sxh[nxt][xr * 12 + xh * 4] =
                make_uint4(hi_pack(pxa.x, pxa.y), hi_pack(pxa.z, pxa.w),
                           hi_pack(pxb.x, pxb.y), hi_pack(pxb.z, pxb.w));
            *(uint4*)&sxl[nxt][xr * 12 + xh * 4] =
                make_uint4(lo_pack(pxa.x, pxa.y), lo_pack(pxa.z, pxa.w),
                           lo_pack(pxb.x, pxb.y), lo_pack(pxb.z, pxb.w));
#pragma unroll
            for (int t = 0; t < 2; t++) {
                int cc = wh * 2 + t;
                swt[nxt][wf * 4 + cc] =
                    make_uint4(hi_pack(pw[t][0], pw[t][1]), hi_pack(pw[t][2], pw[t][3]),
                               lo_pack(pw[t][0], pw[t][1]), lo_pack(pw[t][2], pw[t][3]));
            }
            __syncthreads();
        }
    }

    // ---- epilogue: store h fp32 + e_src/e_dst reductions ----
    const int gr0 = R0 + wid * 16 + q;
#pragma unroll
    for (int nt = 0; nt < 16; nt++) {
        const int gc = F0 + nt * 8 + 2 * c;
        *(float2*)(g_h + (size_t)gr0 * OUT_ + gc)       = make_float2(acc[nt][0], acc[nt][1]);
        *(float2*)(g_h + (size_t)(gr0 + 8) * OUT_ + gc) = make_float2(acc[nt][2], acc[nt][3]);
    }

    const int b = gr0 >> 10;
    const int n = gr0 & (N_ - 1);
#pragma unroll
    for (int hh = 0; hh < 2; hh++) {
        float ps0 = 0.f, ps1 = 0.f, pd0 = 0.f, pd1 = 0.f;
#pragma unroll
        for (int t = 0; t < 8; t++) {
            const int nt = hh * 8 + t;
            const int gc = F0 + nt * 8 + 2 * c;
            float2 as2 = *(float2*)&sAs[gc];
            float2 ad2 = *(float2*)&sAd[gc];
            ps0 += acc[nt][0] * as2.x + acc[nt][1] * as2.y;
            ps1 += acc[nt][2] * as2.x + acc[nt][3] * as2.y;
            pd0 += acc[nt][0] * ad2.x + acc[nt][1] * ad2.y;
            pd1 += acc[nt][2] * ad2.x + acc[nt][3] * ad2.y;
        }
#pragma unroll
        for (int off = 1; off <= 2; off <<= 1) {
            ps0 += __shfl_xor_sync(0xffffffffu, ps0, off);
            ps1 += __shfl_xor_sync(0xffffffffu, ps1, off);
            pd0 += __shfl_xor_sync(0xffffffffu, pd0, off);
            pd1 += __shfl_xor_sync(0xffffffffu, pd1, off);
        }
        if (c == 0) {
            const int hd = blockIdx.y * 2 + hh;
            g_esrc[(b * H_ + hd) * N_ + n]     = ps0;
            g_esrc[(b * H_ + hd) * N_ + n + 8] = ps1;
            g_edst[(b * H_ + hd) * N_ + n]     = pd0;
            g_edst[(b * H_ + hd) * N_ + n + 8] = pd1;
        }
    }
}

// ============================================================================
// Kernel 1b: transpose + split + pack h -> g_hTi (R13, unchanged).
// ============================================================================
__global__ __launch_bounds__(256) void transpose_pack_kernel()
{
    __shared__ float h_t[64 * 65];

    const int bid = blockIdx.x;
    const int hd  = bid & 3;
    const int jb  = (bid >> 2) & 15;
    const int b   = bid >> 6;
    const int tid = threadIdx.x;

    for (int idx = tid; idx < 1024; idx += 256) {
        int j  = idx >> 4;
        int f4 = idx & 15;
        float4 v = *(const float4*)(g_h + (size_t)(b * N_ + jb * 64 + j) * OUT_ + hd * 64 + f4 * 4);
        h_t[(f4 * 4 + 0) * 65 + j] = v.x;
        h_t[(f4 * 4 + 1) * 65 + j] = v.y;
        h_t[(f4 * 4 + 2) * 65 + j] = v.z;
        h_t[(f4 * 4 + 3) * 65 + j] = v.w;
    }
    __syncthreads();

    const int chunk = jb >> 1;
    const int half  = jb & 1;
    uint4* gt = g_hTi + ((size_t)((b * H_ + hd) * 8 + chunk)) * 2048;

    const int f = tid >> 2;
#pragma unroll
    for (int v = 0; v < 4; v++) {
        const int colL = (tid & 3) * 4 + v;
        const int ktL  = colL >> 2;
        const int cc   = colL & 3;
        const int jL   = ktL * 16 + 2 * cc;
        float a0 = h_t[f * 65 + jL];
        float a1 = h_t[f * 65 + jL + 1];
        float a2 = h_t[f * 65 + jL + 8];
        float a3 = h_t[f * 65 + jL + 9];
        gt[f * 32 + half * 16 + colL] =
            make_uint4(hi_pack(a0, a1), hi_pack(a2, a3),
                       lo_pack(a0, a1), lo_pack(a2, a3));
    }
}

// ============================================================================
// Kernel 2: HMMA flash-GAT (R13 verbatim — measured 138 us in the 194.6 run).
// Head-split 2 heads/CTA, abits in smem, pure-copy B staging.
// CTA = (b, 128 i-rows, 2 heads); grid.z = 2; 8 warps.
// ============================================================================
#define HBI_STR 36

__global__ __launch_bounds__(256, 2) void gat_attn_mma_kernel(
    const float* __restrict__ adj, const float* __restrict__ bias,
    float* __restrict__ out)
{
    __shared__ uint32_t abits[128][4];
    __shared__ float    es_sh[2][128];
    __shared__ float    ed_sh[2][128];
    __shared__ __align__(16) uint4 hbi[64 * HBI_STR];

    const int tid = threadIdx.x;
    const int wid = tid >> 5;
    const int l   = tid & 31;
    const int q   = l >> 2;
    const int c   = l & 3;
    const int b   = blockIdx.y;
    const int i0  = blockIdx.x * 128;
    const int hp  = blockIdx.z;          // head pair: heads hp*2, hp*2+1

    for (int idx = tid; idx < 2 * 128; idx += 256)
        ed_sh[idx >> 7][idx & 127] =
            g_edst[(b * H_ + hp * 2 + (idx >> 7)) * N_ + i0 + (idx & 127)];

    float acc[2][8][4];
    float den[2][2];
#pragma unroll
    for (int hh = 0; hh < 2; hh++) {
        den[hh][0] = 0.f; den[hh][1] = 0.f;
#pragma unroll
        for (int nt = 0; nt < 8; nt++)
#pragma unroll
            for (int k = 0; k < 4; k++) acc[hh][nt][k] = 0.f;
    }

    const float* adj_b = adj + (size_t)b * N_ * N_;

    for (int chunk = 0; chunk < 8; chunk++) {
        const int j0 = chunk * 128;
        __syncthreads();

        // adjacency bitmask: warp w handles its own 16 rows
#pragma unroll 4
        for (int k = 0; k < 16; k++) {
            int r = wid * 16 + k;
            const float* arow = adj_b + (size_t)(i0 + r) * N_ + j0;
#pragma unroll
            for (int jg = 0; jg < 4; jg++) {
                uint32_t m = __ballot_sync(0xffffffffu, arow[jg * 32 + l] > 0.5f);
                if (l == 0) abits[r][jg] = m;
            }
        }
        for (int idx = tid; idx < 2 * 128; idx += 256)
            es_sh[idx >> 7][idx & 127] =
                g_esrc[(b * H_ + hp * 2 + (idx >> 7)) * N_ + j0 + (idx & 127)];

#pragma unroll
        for (int hh = 0; hh < 2; hh++) {
            __syncthreads();
            // stage packed B fragments: pure copy, coalesced src, CF dst
            {
                const uint4* gt = g_hTi +
                    ((size_t)((b * H_ + hp * 2 + hh) * 8 + chunk)) * 2048;
#pragma unroll
                for (int v = 0; v < 8; v++) {
                    int idx = tid + v * 256;            // 0..2047
                    int f = idx >> 5, col = idx & 31;
                    hbi[f * HBI_STR + col] = gt[idx];
                }
            }
            __syncthreads();

            const int r0 = wid * 16 + q;
            const float ed0 = ed_sh[hh][r0];
            const float ed1 = ed_sh[hh][r0 + 8];
            float dsum0 = 0.f, dsum1 = 0.f;
#pragma unroll
            for (int kt = 0; kt < 8; kt++) {
                const int jA = kt * 16 + c * 2;
                float2 eA = *(const float2*)&es_sh[hh][jA];
                float2 eB = *(const float2*)&es_sh[hh][jA + 8];
                const uint32_t w0 = abits[r0][kt >> 1];
                const uint32_t w1 = abits[r0 + 8][kt >> 1];
                const int bb = ((kt & 1) << 4) + c * 2;

                float p00, p01, p08, p09, p10, p11, p18, p19;
                {
                    float s;
                    s = ed0 + eA.x; s = fmaxf(s, 0.2f * s); p00 = ((w0 >> bb) & 1u) ? __expf(s) : 0.f;
                    s = ed0 + eA.y; s = fmaxf(s, 0.2f * s); p01 = ((w0 >> (bb + 1)) & 1u) ? __expf(s) : 0.f;
                    s = ed0 + eB.x; s = fmaxf(s, 0.2f * s); p08 = ((w0 >> (bb + 8)) & 1u) ? __expf(s) : 0.f;
                    s = ed0 + eB.y; s = fmaxf(s, 0.2f * s); p09 = ((w0 >> (bb + 9)) & 1u) ? __expf(s) : 0.f;
                    s = ed1 + eA.x; s = fmaxf(s, 0.2f * s); p10 = ((w1 >> bb) & 1u) ? __expf(s) : 0.f;
                    s = ed1 + eA.y; s = fmaxf(s, 0.2f * s); p11 = ((w1 >> (bb + 1)) & 1u) ? __expf(s) : 0.f;
                    s = ed1 + eB.x; s = fmaxf(s, 0.2f * s); p18 = ((w1 >> (bb + 8)) & 1u) ? __expf(s) : 0.f;
                    s = ed1 + eB.y; s = fmaxf(s, 0.2f * s); p19 = ((w1 >> (bb + 9)) & 1u) ? __expf(s) : 0.f;
                }
                dsum0 += (p00 + p01) + (p08 + p09);
                dsum1 += (p10 + p11) + (p18 + p19);

                const uint32_t a0h = hi_pack(p00, p01), a1h = hi_pack(p10, p11);
                const uint32_t a2h = hi_pack(p08, p09), a3h = hi_pack(p18, p19);
                const uint32_t a0l = lo_pack(p00, p01), a1l = lo_pack(p10, p11);
                const uint32_t a2l = lo_pack(p08, p09), a3l = lo_pack(p18, p19);

#pragma unroll
                for (int nt = 0; nt < 8; nt++) {
                    uint4 v = hbi[(nt * 8 + q) * HBI_STR + kt * 4 + c];
                    mma16816(acc[hh][nt], a0h, a1h, a2h, a3h, v.x, v.y);
                    mma16816(acc[hh][nt], a0h, a1h, a2h, a3h, v.z, v.w);
                    mma16816(acc[hh][nt], a0l, a1l, a2l, a3l, v.x, v.y);
                }
            }
            den[hh][0] += dsum0;
            den[hh][1] += dsum1;
        }
    }

    // ---- epilogue: out = acc / den + bias ----
    const int gr0 = b * N_ + i0 + wid * 16 + q;
#pragma unroll
    for (int hh = 0; hh < 2; hh++) {
        float d0 = den[hh][0];
        d0 += __shfl_xor_sync(0xffffffffu, d0, 1);
        d0 += __shfl_xor_sync(0xffffffffu, d0, 2);
        float d1 = den[hh][1];
        d1 += __shfl_xor_sync(0xffffffffu, d1, 1);
        d1 += __shfl_xor_sync(0xffffffffu, d1, 2);
        const float rl0 = 1.0f / d0, rl1 = 1.0f / d1;
#pragma unroll
        for (int nt = 0; nt < 8; nt++) {
            const int col = (hp * 2 + hh) * 64 + nt * 8 + c * 2;
            float2 bv = __ldg((const float2*)(bias + col));
            float2 o0, o1;
            o0.x = acc[hh][nt][0] * rl0 + bv.x;
            o0.y = acc[hh][nt][1] * rl0 + bv.y;
            o1.x = acc[hh][nt][2] * rl1 + bv.x;
            o1.y = acc[hh][nt][3] * rl1 + bv.y;
            *(float2*)(out + (size_t)gr0 * OUT_ + col)       = o0;
            *(float2*)(out + (size_t)(gr0 + 8) * OUT_ + col) = o1;
        }
    }
}

// ============================================================================
extern "C" void kernel_launch(void* const* d_in, const int* in_sizes, int n_in,
                              void* d_out, int out_size)
{
    const float* x     = (const float*)d_in[0];
    const float* adj   = (const float*)d_in[1];
    const float* W     = (const float*)d_in[2];
    const float* a_src = (const float*)d_in[3];
    const float* a_dst = (const float*)d_in[4];
    const float* bias  = (const float*)d_in[5];
    float* out = (float*)d_out;

    gemm_h_mma_kernel<<<dim3((B_ * N_) / 128, 2), 256>>>(x, W, a_src, a_dst);
    transpose_pack_kernel<<<B_ * 16 * H_, 256>>>();
    gat_attn_mma_kernel<<<dim3(N_ / 128, B_, 2), 256>>>(adj, bias, out);
}